// round 1
// baseline (speedup 1.0000x reference)
#include <cuda_runtime.h>
#include <cuda_bf16.h>
#include <math.h>

// Problem constants
#define B   16
#define C   384
#define HD  8
#define DC  48
#define HW  4096
#define QC  192
#define KVC 768

// Scratch (device globals; allocation in kernel_launch is forbidden)
__device__ float g_kv[(long long)B * KVC * HW];   // 201 MB: k = [:,0:384,:], v = [:,384:768,:]
__device__ float g_q [(long long)B * C   * HW];   // 100 MB
__device__ float g_o [(long long)B * C   * HW];   // 100 MB (attention output, pre-proj)
__device__ float g_invq[B * C];
__device__ float g_invk[B * C];

// ---------------------------------------------------------------------------
// Generic batched SGEMM: C[b] = A (MxK, shared) * B[b] (KxN), row-major.
// BM=BN=128, BK=16, 256 threads, 8x8 per thread.
// Requires M%128==0, N%128==0, K%16==0 (true for all three uses).
// ---------------------------------------------------------------------------
#define BM 128
#define BN 128
#define BK 16

__global__ __launch_bounds__(256) void sgemm_kernel(
    const float* __restrict__ A, const float* __restrict__ Bg, float* __restrict__ Cg,
    int M, int N, int K, long long bStride, long long cStride)
{
    const float* Bp = Bg + (long long)blockIdx.z * bStride;
    float*       Cp = Cg + (long long)blockIdx.z * cStride;
    const int m0 = blockIdx.y * BM;
    const int n0 = blockIdx.x * BN;

    __shared__ float As[BK][BM];
    __shared__ float Bs[BK][BN];

    const int tid = threadIdx.x;
    const int tm = tid >> 4;     // 0..15
    const int tn = tid & 15;     // 0..15

    float acc[8][8] = {};

    for (int k0 = 0; k0 < K; k0 += BK) {
        // A tile: 128x16 -> transposed As[k][m]
        for (int i = tid; i < (BM * BK) / 4; i += 256) {
            int row = i >> 2;          // 4 float4 per 16-wide row
            int c4  = i & 3;
            float4 v = *(const float4*)&A[(long long)(m0 + row) * K + k0 + c4 * 4];
            As[c4 * 4 + 0][row] = v.x;
            As[c4 * 4 + 1][row] = v.y;
            As[c4 * 4 + 2][row] = v.z;
            As[c4 * 4 + 3][row] = v.w;
        }
        // B tile: 16x128 direct
        for (int i = tid; i < (BK * BN) / 4; i += 256) {
            int row = i >> 5;          // 32 float4 per 128-wide row
            int c4  = i & 31;
            *(float4*)&Bs[row][c4 * 4] =
                *(const float4*)&Bp[(long long)(k0 + row) * N + n0 + c4 * 4];
        }
        __syncthreads();

        #pragma unroll
        for (int kk = 0; kk < BK; kk++) {
            float4 a0 = *(const float4*)&As[kk][tm * 8];
            float4 a1 = *(const float4*)&As[kk][tm * 8 + 4];
            float4 b0 = *(const float4*)&Bs[kk][tn * 8];
            float4 b1 = *(const float4*)&Bs[kk][tn * 8 + 4];
            float ra[8] = {a0.x, a0.y, a0.z, a0.w, a1.x, a1.y, a1.z, a1.w};
            float rb[8] = {b0.x, b0.y, b0.z, b0.w, b1.x, b1.y, b1.z, b1.w};
            #pragma unroll
            for (int i = 0; i < 8; i++)
                #pragma unroll
                for (int j = 0; j < 8; j++)
                    acc[i][j] = fmaf(ra[i], rb[j], acc[i][j]);
        }
        __syncthreads();
    }

    #pragma unroll
    for (int i = 0; i < 8; i++) {
        long long r = (long long)(m0 + tm * 8 + i) * N + n0 + tn * 8;
        *(float4*)&Cp[r]     = make_float4(acc[i][0], acc[i][1], acc[i][2], acc[i][3]);
        *(float4*)&Cp[r + 4] = make_float4(acc[i][4], acc[i][5], acc[i][6], acc[i][7]);
    }
}

// ---------------------------------------------------------------------------
// Row L2-norm reciprocals: invq over g_q rows, invk over k-part of g_kv rows.
// One block per row (2 * B * C rows of 4096 floats).
// ---------------------------------------------------------------------------
__global__ __launch_bounds__(256) void norm_kernel(
    const float* __restrict__ qbuf, const float* __restrict__ kvbuf,
    float* __restrict__ invq, float* __restrict__ invk)
{
    const int r   = blockIdx.x;
    const int isK = (r >= B * C) ? 1 : 0;
    const int rr  = isK ? r - B * C : r;
    const int b   = rr / C;
    const int c   = rr % C;
    const float* src = isK ? kvbuf + ((long long)b * KVC + c) * HW
                           : qbuf  + ((long long)b * C   + c) * HW;
    const int tid = threadIdx.x;

    float s = 0.f;
    for (int i = tid * 4; i < HW; i += 256 * 4) {
        float4 v = *(const float4*)&src[i];
        s += v.x * v.x + v.y * v.y + v.z * v.z + v.w * v.w;
    }
    #pragma unroll
    for (int o = 16; o; o >>= 1) s += __shfl_xor_sync(0xffffffffu, s, o);

    __shared__ float red[8];
    if ((tid & 31) == 0) red[tid >> 5] = s;
    __syncthreads();
    if (tid < 8) {
        s = red[tid];
        #pragma unroll
        for (int o = 4; o; o >>= 1) s += __shfl_xor_sync(0xffu, s, o);
        if (tid == 0) {
            float inv = 1.0f / fmaxf(sqrtf(s), 1e-12f);
            (isK ? invk : invq)[rr] = inv;
        }
    }
}

// ---------------------------------------------------------------------------
// Fused per-(b,h) channel attention: S = (Q Kt) * invq*invk*temp; softmax; O = S V.
// One block per (b,h) -> 128 blocks, 256 threads.
// ---------------------------------------------------------------------------
__global__ __launch_bounds__(256) void attn_kernel(
    const float* __restrict__ qbuf, const float* __restrict__ kvbuf,
    const float* __restrict__ invq, const float* __restrict__ invk,
    const float* __restrict__ temperature, float* __restrict__ obuf)
{
    const int bh = blockIdx.x;
    const int b  = bh >> 3;
    const int h  = bh & 7;
    const float* q = qbuf  + ((long long)b * C   + h * DC) * HW;
    const float* k = kvbuf + ((long long)b * KVC + h * DC) * HW;
    const float* v = kvbuf + ((long long)b * KVC + C + h * DC) * HW;
    float*       o = obuf  + ((long long)b * C   + h * DC) * HW;

    __shared__ float QsT[64][49];
    __shared__ float KsT[64][49];
    __shared__ float S[48][49];
    __shared__ float Vs[48][68];   // 68 -> rows 16B-aligned for float4 LDS

    const int tid = threadIdx.x;
    const int tm = tid >> 4;   // 0..15 -> 3 rows
    const int tn = tid & 15;   // 0..15 -> 3 cols (phase1) / 4 cols (phase2)

    // ---- Phase 1: S = Q * K^T over spatial (4096) ----
    float acc[3][3] = {};
    for (int n0 = 0; n0 < HW; n0 += 64) {
        for (int i = tid; i < DC * 64; i += 256) {
            int c  = i >> 6;
            int nn = i & 63;
            QsT[nn][c] = q[(long long)c * HW + n0 + nn];
            KsT[nn][c] = k[(long long)c * HW + n0 + nn];
        }
        __syncthreads();
        #pragma unroll 8
        for (int kk = 0; kk < 64; kk++) {
            float ra[3], rb[3];
            #pragma unroll
            for (int i = 0; i < 3; i++) ra[i] = QsT[kk][tm * 3 + i];
            #pragma unroll
            for (int j = 0; j < 3; j++) rb[j] = KsT[kk][tn * 3 + j];
            #pragma unroll
            for (int i = 0; i < 3; i++)
                #pragma unroll
                for (int j = 0; j < 3; j++)
                    acc[i][j] = fmaf(ra[i], rb[j], acc[i][j]);
        }
        __syncthreads();
    }

    // scale by 1/||q|| * 1/||k|| * temperature[h], stage into smem
    {
        const float t = temperature[h];
        float iq[3], ik[3];
        #pragma unroll
        for (int i = 0; i < 3; i++) iq[i] = invq[b * C + h * DC + tm * 3 + i];
        #pragma unroll
        for (int j = 0; j < 3; j++) ik[j] = invk[b * C + h * DC + tn * 3 + j];
        #pragma unroll
        for (int i = 0; i < 3; i++)
            #pragma unroll
            for (int j = 0; j < 3; j++)
                S[tm * 3 + i][tn * 3 + j] = acc[i][j] * iq[i] * ik[j] * t;
    }
    __syncthreads();

    // ---- Softmax over rows (48x48, tiny) ----
    if (tid < DC) {
        float m = -INFINITY;
        for (int d = 0; d < DC; d++) m = fmaxf(m, S[tid][d]);
        float sum = 0.f;
        for (int d = 0; d < DC; d++) {
            float e = expf(S[tid][d] - m);
            S[tid][d] = e;
            sum += e;
        }
        float inv = 1.0f / sum;
        for (int d = 0; d < DC; d++) S[tid][d] *= inv;
    }
    __syncthreads();

    // ---- Phase 2: O = S * V ----
    const int tn4 = tn * 4;
    for (int n0 = 0; n0 < HW; n0 += 64) {
        for (int i = tid; i < DC * 64; i += 256) {
            int d  = i >> 6;
            int nn = i & 63;
            Vs[d][nn] = v[(long long)d * HW + n0 + nn];
        }
        __syncthreads();
        float acc2[3][4] = {};
        #pragma unroll 4
        for (int d = 0; d < DC; d++) {
            float rs[3];
            #pragma unroll
            for (int i = 0; i < 3; i++) rs[i] = S[tm * 3 + i][d];
            float4 rv = *(const float4*)&Vs[d][tn4];
            #pragma unroll
            for (int i = 0; i < 3; i++) {
                acc2[i][0] = fmaf(rs[i], rv.x, acc2[i][0]);
                acc2[i][1] = fmaf(rs[i], rv.y, acc2[i][1]);
                acc2[i][2] = fmaf(rs[i], rv.z, acc2[i][2]);
                acc2[i][3] = fmaf(rs[i], rv.w, acc2[i][3]);
            }
        }
        #pragma unroll
        for (int i = 0; i < 3; i++) {
            *(float4*)&o[(long long)(tm * 3 + i) * HW + n0 + tn4] =
                make_float4(acc2[i][0], acc2[i][1], acc2[i][2], acc2[i][3]);
        }
        __syncthreads();
    }
}

// ---------------------------------------------------------------------------
// Launch
// ---------------------------------------------------------------------------
extern "C" void kernel_launch(void* const* d_in, const int* in_sizes, int n_in,
                              void* d_out, int out_size)
{
    const float* x           = (const float*)d_in[0];
    const float* query       = (const float*)d_in[1];
    const float* w_kv        = (const float*)d_in[2];
    const float* w_q         = (const float*)d_in[3];
    const float* w_proj      = (const float*)d_in[4];
    const float* temperature = (const float*)d_in[5];
    float* out = (float*)d_out;

    float *kv, *qb, *ob, *invq, *invk;
    cudaGetSymbolAddress((void**)&kv,   g_kv);
    cudaGetSymbolAddress((void**)&qb,   g_q);
    cudaGetSymbolAddress((void**)&ob,   g_o);
    cudaGetSymbolAddress((void**)&invq, g_invq);
    cudaGetSymbolAddress((void**)&invk, g_invk);

    // 1) kv = w_kv @ x   (per batch: [768,4096] = [768,384]x[384,4096])
    sgemm_kernel<<<dim3(HW / BN, KVC / BM, B), 256>>>(
        w_kv, x, kv, KVC, HW, C, (long long)C * HW, (long long)KVC * HW);

    // 2) q = w_q @ query (per batch: [384,4096] = [384,192]x[192,4096])
    sgemm_kernel<<<dim3(HW / BN, C / BM, B), 256>>>(
        w_q, query, qb, C, HW, QC, (long long)QC * HW, (long long)C * HW);

    // 3) row norms of q and k
    norm_kernel<<<2 * B * C, 256>>>(qb, kv, invq, invk);

    // 4) fused channel attention per (b, head)
    attn_kernel<<<B * HD, 256>>>(qb, kv, invq, invk, temperature, ob);

    // 5) out = w_proj @ o (per batch: [384,4096] = [384,384]x[384,4096])
    sgemm_kernel<<<dim3(HW / BN, C / BM, B), 256>>>(
        w_proj, ob, out, C, HW, C, (long long)C * HW, (long long)C * HW);
}

// round 2
// speedup vs baseline: 1.2239x; 1.2239x over previous
#include <cuda_runtime.h>
#include <cuda_bf16.h>
#include <math.h>

// Problem constants
#define B   16
#define C   384
#define HD  8
#define DC  48
#define HW  4096
#define QC  192
#define KVC 768

#define NCHUNK_QK 8     // spatial chunks for QK^T partials
#define NCHUNK_SV 16    // spatial chunks for S*V

// Scratch (device globals)
__device__ float g_kv [(long long)B * KVC * HW];   // k = [:,0:384,:], v = [:,384:768,:]
__device__ float g_q  [(long long)B * C   * HW];
__device__ float g_o  [(long long)B * C   * HW];
__device__ float g_Sp [NCHUNK_QK * B * HD * DC * DC];  // QK^T partials
__device__ float g_ssp[NCHUNK_QK * B * HD * 2 * DC];   // sumsq partials (q rows then k rows)
__device__ float g_S  [B * HD * DC * DC];              // softmaxed attention

// ---------------------------------------------------------------------------
// f32x2 packed helpers (Blackwell)
// ---------------------------------------------------------------------------
__device__ __forceinline__ unsigned long long pk2(float a, float b) {
    unsigned long long r;
    asm("mov.b64 %0, {%1, %2};" : "=l"(r) : "f"(a), "f"(b));
    return r;
}
__device__ __forceinline__ unsigned long long fma2(unsigned long long a,
                                                   unsigned long long b,
                                                   unsigned long long c) {
    unsigned long long d;
    asm("fma.rn.f32x2 %0, %1, %2, %3;" : "=l"(d) : "l"(a), "l"(b), "l"(c));
    return d;
}
__device__ __forceinline__ void unpk2(unsigned long long v, float& a, float& b) {
    asm("mov.b64 {%0, %1}, %2;" : "=f"(a), "=f"(b) : "l"(v));
}

// ---------------------------------------------------------------------------
// Batched SGEMM: C[b] = A (MxK, shared across batch) * B[b] (KxN), row-major.
// BM=BN=128, BK=16, 256 threads, 8x8 per thread, f32x2 packed inner loop.
// ---------------------------------------------------------------------------
#define BM 128
#define BN 128
#define BK 16

__global__ __launch_bounds__(256) void sgemm_kernel(
    const float* __restrict__ A, const float* __restrict__ Bg, float* __restrict__ Cg,
    int M, int N, int K, long long bStride, long long cStride)
{
    const float* Bp = Bg + (long long)blockIdx.z * bStride;
    float*       Cp = Cg + (long long)blockIdx.z * cStride;
    const int m0 = blockIdx.y * BM;
    const int n0 = blockIdx.x * BN;

    __shared__ float As[BK][BM];
    __shared__ float Bs[BK][BN];

    const int tid = threadIdx.x;
    const int tm = tid >> 4;
    const int tn = tid & 15;

    unsigned long long acc[8][4];
    #pragma unroll
    for (int i = 0; i < 8; i++)
        #pragma unroll
        for (int j = 0; j < 4; j++) acc[i][j] = 0ull;

    for (int k0 = 0; k0 < K; k0 += BK) {
        for (int i = tid; i < (BM * BK) / 4; i += 256) {
            int row = i >> 2;
            int c4  = i & 3;
            float4 v = *(const float4*)&A[(long long)(m0 + row) * K + k0 + c4 * 4];
            As[c4 * 4 + 0][row] = v.x;
            As[c4 * 4 + 1][row] = v.y;
            As[c4 * 4 + 2][row] = v.z;
            As[c4 * 4 + 3][row] = v.w;
        }
        for (int i = tid; i < (BK * BN) / 4; i += 256) {
            int row = i >> 5;
            int c4  = i & 31;
            *(float4*)&Bs[row][c4 * 4] =
                *(const float4*)&Bp[(long long)(k0 + row) * N + n0 + c4 * 4];
        }
        __syncthreads();

        #pragma unroll
        for (int kk = 0; kk < BK; kk++) {
            float4 a0 = *(const float4*)&As[kk][tm * 8];
            float4 a1 = *(const float4*)&As[kk][tm * 8 + 4];
            float4 b0 = *(const float4*)&Bs[kk][tn * 8];
            float4 b1 = *(const float4*)&Bs[kk][tn * 8 + 4];
            unsigned long long bp[4];
            bp[0] = pk2(b0.x, b0.y);
            bp[1] = pk2(b0.z, b0.w);
            bp[2] = pk2(b1.x, b1.y);
            bp[3] = pk2(b1.z, b1.w);
            float ra[8] = {a0.x, a0.y, a0.z, a0.w, a1.x, a1.y, a1.z, a1.w};
            #pragma unroll
            for (int i = 0; i < 8; i++) {
                unsigned long long ai = pk2(ra[i], ra[i]);
                #pragma unroll
                for (int j = 0; j < 4; j++)
                    acc[i][j] = fma2(ai, bp[j], acc[i][j]);
            }
        }
        __syncthreads();
    }

    #pragma unroll
    for (int i = 0; i < 8; i++) {
        float o[8];
        #pragma unroll
        for (int j = 0; j < 4; j++) unpk2(acc[i][j], o[2 * j], o[2 * j + 1]);
        long long r = (long long)(m0 + tm * 8 + i) * N + n0 + tn * 8;
        *(float4*)&Cp[r]     = make_float4(o[0], o[1], o[2], o[3]);
        *(float4*)&Cp[r + 4] = make_float4(o[4], o[5], o[6], o[7]);
    }
}

// ---------------------------------------------------------------------------
// QK^T partials + sumsq partials. grid = (NCHUNK_QK, B*HD), 256 threads.
// Each block: 48x48 partial over HW/NCHUNK_QK spatial positions.
// ---------------------------------------------------------------------------
__global__ __launch_bounds__(256) void qk_partial_kernel(
    const float* __restrict__ qbuf, const float* __restrict__ kvbuf,
    float* __restrict__ Sp, float* __restrict__ ssp)
{
    const int chunk = blockIdx.x;
    const int bh = blockIdx.y;
    const int b  = bh >> 3;
    const int h  = bh & 7;
    const float* q = qbuf  + ((long long)b * C   + h * DC) * HW;
    const float* k = kvbuf + ((long long)b * KVC + h * DC) * HW;
    const int nbase = chunk * (HW / NCHUNK_QK);

    __shared__ float QsT[64][49];
    __shared__ float KsT[64][49];

    const int tid = threadIdx.x;
    const int tm = tid >> 4;
    const int tn = tid & 15;

    float acc[3][3] = {};
    float ssq = 0.f;   // used by tid < 96

    for (int t = 0; t < (HW / NCHUNK_QK); t += 64) {
        const int n0 = nbase + t;
        for (int i = tid; i < DC * 64; i += 256) {
            int c  = i >> 6;
            int nn = i & 63;
            QsT[nn][c] = q[(long long)c * HW + n0 + nn];
            KsT[nn][c] = k[(long long)c * HW + n0 + nn];
        }
        __syncthreads();
        #pragma unroll 8
        for (int kk = 0; kk < 64; kk++) {
            float ra[3], rb[3];
            #pragma unroll
            for (int i = 0; i < 3; i++) ra[i] = QsT[kk][tm * 3 + i];
            #pragma unroll
            for (int j = 0; j < 3; j++) rb[j] = KsT[kk][tn * 3 + j];
            #pragma unroll
            for (int i = 0; i < 3; i++)
                #pragma unroll
                for (int j = 0; j < 3; j++)
                    acc[i][j] = fmaf(ra[i], rb[j], acc[i][j]);
        }
        // sum-of-squares partials from staged smem (threads 0..95)
        if (tid < 2 * DC) {
            const int r = (tid < DC) ? tid : tid - DC;
            #pragma unroll 8
            for (int nn = 0; nn < 64; nn++) {
                float v = (tid < DC) ? QsT[nn][r] : KsT[nn][r];
                ssq = fmaf(v, v, ssq);
            }
        }
        __syncthreads();
    }

    float* Sout = Sp + ((long long)chunk * (B * HD) + bh) * (DC * DC);
    #pragma unroll
    for (int i = 0; i < 3; i++)
        #pragma unroll
        for (int j = 0; j < 3; j++)
            Sout[(tm * 3 + i) * DC + tn * 3 + j] = acc[i][j];

    if (tid < 2 * DC)
        ssp[((long long)chunk * (B * HD) + bh) * (2 * DC) + tid] = ssq;
}

// ---------------------------------------------------------------------------
// Reduce partials, apply norms + temperature, softmax. 128 blocks, 256 thr.
// ---------------------------------------------------------------------------
__global__ __launch_bounds__(256) void softmax_kernel(
    const float* __restrict__ Sp, const float* __restrict__ ssp,
    const float* __restrict__ temperature, float* __restrict__ Sout)
{
    const int bh = blockIdx.x;
    const int h  = bh & 7;
    const int tid = threadIdx.x;

    __shared__ float S[DC][DC + 1];
    __shared__ float invq[DC], invk[DC];

    // reduce S partials
    for (int i = tid; i < DC * DC; i += 256) {
        float s = 0.f;
        #pragma unroll
        for (int ch = 0; ch < NCHUNK_QK; ch++)
            s += Sp[((long long)ch * (B * HD) + bh) * (DC * DC) + i];
        S[i / DC][i % DC] = s;
    }
    // reduce sumsq partials -> inverse norms
    if (tid < 2 * DC) {
        float s = 0.f;
        #pragma unroll
        for (int ch = 0; ch < NCHUNK_QK; ch++)
            s += ssp[((long long)ch * (B * HD) + bh) * (2 * DC) + tid];
        float inv = 1.0f / fmaxf(sqrtf(s), 1e-12f);
        if (tid < DC) invq[tid] = inv; else invk[tid - DC] = inv;
    }
    __syncthreads();

    if (tid < DC) {
        const float t = temperature[h];
        const float iq = invq[tid] * t;
        float m = -INFINITY;
        float row[DC];
        #pragma unroll 8
        for (int d = 0; d < DC; d++) {
            float v = S[tid][d] * iq * invk[d];
            row[d] = v;
            m = fmaxf(m, v);
        }
        float sum = 0.f;
        #pragma unroll 8
        for (int d = 0; d < DC; d++) {
            float e = expf(row[d] - m);
            row[d] = e;
            sum += e;
        }
        float inv = 1.0f / sum;
        #pragma unroll 8
        for (int d = 0; d < DC; d++)
            Sout[(long long)bh * (DC * DC) + tid * DC + d] = row[d] * inv;
    }
}

// ---------------------------------------------------------------------------
// O = S * V, spatial-split. grid = (NCHUNK_SV, B*HD), 256 threads.
// ---------------------------------------------------------------------------
__global__ __launch_bounds__(256) void sv_kernel(
    const float* __restrict__ Sg, const float* __restrict__ kvbuf,
    float* __restrict__ obuf)
{
    const int chunk = blockIdx.x;
    const int bh = blockIdx.y;
    const int b  = bh >> 3;
    const int h  = bh & 7;
    const float* v = kvbuf + ((long long)b * KVC + C + h * DC) * HW;
    float*       o = obuf  + ((long long)b * C   + h * DC) * HW;
    const int nbase = chunk * (HW / NCHUNK_SV);

    __shared__ float S[DC][DC + 1];
    __shared__ float Vs[DC][68];

    const int tid = threadIdx.x;
    const int tm = tid >> 4;
    const int tn = tid & 15;
    const int tn4 = tn * 4;

    for (int i = tid; i < DC * DC; i += 256)
        S[i / DC][i % DC] = Sg[(long long)bh * (DC * DC) + i];
    __syncthreads();

    for (int t = 0; t < (HW / NCHUNK_SV); t += 64) {
        const int n0 = nbase + t;
        for (int i = tid; i < DC * 64; i += 256) {
            int d  = i >> 6;
            int nn = i & 63;
            Vs[d][nn] = v[(long long)d * HW + n0 + nn];
        }
        __syncthreads();
        float acc2[3][4] = {};
        #pragma unroll 4
        for (int d = 0; d < DC; d++) {
            float rs[3];
            #pragma unroll
            for (int i = 0; i < 3; i++) rs[i] = S[tm * 3 + i][d];
            float4 rv = *(const float4*)&Vs[d][tn4];
            #pragma unroll
            for (int i = 0; i < 3; i++) {
                acc2[i][0] = fmaf(rs[i], rv.x, acc2[i][0]);
                acc2[i][1] = fmaf(rs[i], rv.y, acc2[i][1]);
                acc2[i][2] = fmaf(rs[i], rv.z, acc2[i][2]);
                acc2[i][3] = fmaf(rs[i], rv.w, acc2[i][3]);
            }
        }
        #pragma unroll
        for (int i = 0; i < 3; i++) {
            *(float4*)&o[(long long)(tm * 3 + i) * HW + n0 + tn4] =
                make_float4(acc2[i][0], acc2[i][1], acc2[i][2], acc2[i][3]);
        }
        __syncthreads();
    }
}

// ---------------------------------------------------------------------------
// Launch
// ---------------------------------------------------------------------------
extern "C" void kernel_launch(void* const* d_in, const int* in_sizes, int n_in,
                              void* d_out, int out_size)
{
    const float* x           = (const float*)d_in[0];
    const float* query       = (const float*)d_in[1];
    const float* w_kv        = (const float*)d_in[2];
    const float* w_q         = (const float*)d_in[3];
    const float* w_proj      = (const float*)d_in[4];
    const float* temperature = (const float*)d_in[5];
    float* out = (float*)d_out;

    float *kv, *qb, *ob, *Sp, *ssp, *S;
    cudaGetSymbolAddress((void**)&kv,  g_kv);
    cudaGetSymbolAddress((void**)&qb,  g_q);
    cudaGetSymbolAddress((void**)&ob,  g_o);
    cudaGetSymbolAddress((void**)&Sp,  g_Sp);
    cudaGetSymbolAddress((void**)&ssp, g_ssp);
    cudaGetSymbolAddress((void**)&S,   g_S);

    // 1) kv = w_kv @ x
    sgemm_kernel<<<dim3(HW / BN, KVC / BM, B), 256>>>(
        w_kv, x, kv, KVC, HW, C, (long long)C * HW, (long long)KVC * HW);

    // 2) q = w_q @ query
    sgemm_kernel<<<dim3(HW / BN, C / BM, B), 256>>>(
        w_q, query, qb, C, HW, QC, (long long)QC * HW, (long long)C * HW);

    // 3) QK^T partials + sumsq partials
    qk_partial_kernel<<<dim3(NCHUNK_QK, B * HD), 256>>>(qb, kv, Sp, ssp);

    // 4) reduce + norm-scale + softmax
    softmax_kernel<<<B * HD, 256>>>(Sp, ssp, temperature, S);

    // 5) O = S * V
    sv_kernel<<<dim3(NCHUNK_SV, B * HD), 256>>>(S, kv, ob);

    // 6) out = w_proj @ o
    sgemm_kernel<<<dim3(HW / BN, C / BM, B), 256>>>(
        w_proj, ob, out, C, HW, C, (long long)C * HW, (long long)C * HW);
}

// round 6
// speedup vs baseline: 2.8124x; 2.2980x over previous
#include <cuda_runtime.h>
#include <cuda_bf16.h>
#include <math.h>
#include <stdint.h>

// Problem constants
#define B   16
#define C   384
#define HD  8
#define DC  48
#define HW  4096
#define QC  192
#define KVC 768

#define NCHUNK_QK 8
#define NCHUNK_SV 16

// Scratch (device globals)
__device__ float g_kv [(long long)B * KVC * HW];
__device__ float g_q  [(long long)B * C   * HW];
__device__ float g_o  [(long long)B * C   * HW];
__device__ float g_Sp [NCHUNK_QK * B * HD * DC * DC];
__device__ float g_ssp[NCHUNK_QK * B * HD * 2 * DC];
__device__ float g_S  [B * HD * DC * DC];

// ---------------------------------------------------------------------------
// mma.sync helpers (sm_80-era PTX; valid on plain sm_100 target)
// ---------------------------------------------------------------------------
__device__ __forceinline__ uint32_t smem_u32(const void* p) {
    uint32_t a;
    asm("{ .reg .u64 t; cvta.to.shared.u64 t, %1; cvt.u32.u64 %0, t; }" : "=r"(a) : "l"(p));
    return a;
}
__device__ __forceinline__ void ldsm_x4(uint32_t r[4], uint32_t addr) {
    asm volatile("ldmatrix.sync.aligned.m8n8.x4.shared.b16 {%0,%1,%2,%3}, [%4];"
                 : "=r"(r[0]), "=r"(r[1]), "=r"(r[2]), "=r"(r[3]) : "r"(addr));
}
__device__ __forceinline__ void ldsm_x4_t(uint32_t r[4], uint32_t addr) {
    asm volatile("ldmatrix.sync.aligned.m8n8.x4.trans.shared.b16 {%0,%1,%2,%3}, [%4];"
                 : "=r"(r[0]), "=r"(r[1]), "=r"(r[2]), "=r"(r[3]) : "r"(addr));
}
__device__ __forceinline__ void mma_bf16(float* c, const uint32_t a[4],
                                         uint32_t b0, uint32_t b1) {
    asm volatile(
        "mma.sync.aligned.m16n8k16.row.col.f32.bf16.bf16.f32 "
        "{%0,%1,%2,%3}, {%4,%5,%6,%7}, {%8,%9}, {%0,%1,%2,%3};"
        : "+f"(c[0]), "+f"(c[1]), "+f"(c[2]), "+f"(c[3])
        : "r"(a[0]), "r"(a[1]), "r"(a[2]), "r"(a[3]), "r"(b0), "r"(b1));
}

// hi/lo bf16 split: x ~= hi + lo, each bf16 (8-bit mantissa) -> ~16 bit total
__device__ __forceinline__ void split_pack(float x0, float x1,
                                           uint32_t& ph, uint32_t& pl) {
    __nv_bfloat16 h0 = __float2bfloat16_rn(x0);
    __nv_bfloat16 h1 = __float2bfloat16_rn(x1);
    __nv_bfloat16 l0 = __float2bfloat16_rn(x0 - __bfloat162float(h0));
    __nv_bfloat16 l1 = __float2bfloat16_rn(x1 - __bfloat162float(h1));
    ph = (uint32_t)__bfloat16_as_ushort(h0) | ((uint32_t)__bfloat16_as_ushort(h1) << 16);
    pl = (uint32_t)__bfloat16_as_ushort(l0) | ((uint32_t)__bfloat16_as_ushort(l1) << 16);
}

// ---------------------------------------------------------------------------
// bf16-split tensor-core GEMM: Out[b][j][s] = sum_k W[j][k] * Act[b][k][s]
// CTA tile 128(j) x 128(s), K-chunk 32. 256 threads = 8 warps (4m x 2n),
// warp tile 32(j) x 64(s). mma m16n8k16, A = W (row-major), B = Act via
// ldmatrix.trans from natural [k][s] staging. out = Ah*Bh + Ah*Bl + Al*Bh.
// ---------------------------------------------------------------------------
#define WPITCH 40    // bf16 elems per row of W tile (80B -> conflict-free ldmatrix)
#define APITCH 136   // bf16 elems per row of Act tile (272B -> conflict-free trans)

template<int K>
__global__ __launch_bounds__(256, 2) void gemm_bf16s_kernel(
    const float* __restrict__ W, const float* __restrict__ Act,
    float* __restrict__ Out, int OCtot)
{
    __shared__ __align__(16) uint16_t sWh[128 * WPITCH];
    __shared__ __align__(16) uint16_t sWl[128 * WPITCH];
    __shared__ __align__(16) uint16_t sAh[32 * APITCH];
    __shared__ __align__(16) uint16_t sAl[32 * APITCH];

    const int tid  = threadIdx.x;
    const int warp = tid >> 5;
    const int lane = tid & 31;
    const int s0 = blockIdx.x * 128;
    const int j0 = blockIdx.y * 128;
    const int b  = blockIdx.z;

    const float* Ap = Act + (long long)b * K * HW;
    float*       Op = Out + ((long long)b * OCtot + j0) * HW + s0;

    const int mbase = (warp >> 1) * 32;   // warp row base within tile
    const int nbase = (warp & 1) * 64;    // warp col base within tile

    const uint32_t uWh = smem_u32(sWh);
    const uint32_t uWl = smem_u32(sWl);
    const uint32_t uAh = smem_u32(sAh);
    const uint32_t uAl = smem_u32(sAl);

    float acc[64];
    #pragma unroll
    for (int i = 0; i < 64; i++) acc[i] = 0.f;

    // precomputed ldmatrix address components
    const int lrow = (lane & 7) + ((lane >> 3) & 1) * 8;   // row within 16-row block
    const int lhalf = lane >> 4;                           // 0/1: second 8-wide block

    for (int k0 = 0; k0 < K; k0 += 32) {
        // ---- stage W tile [128 j][32 k] hi/lo ----
        #pragma unroll
        for (int i = 0; i < 4; i++) {
            int idx = i * 256 + tid;       // 0..1023 float4s
            int j = idx >> 3;
            int q = idx & 7;
            float4 v = *(const float4*)&W[(long long)(j0 + j) * K + k0 + q * 4];
            uint32_t h0, l0, h1, l1;
            split_pack(v.x, v.y, h0, l0);
            split_pack(v.z, v.w, h1, l1);
            *(uint2*)&sWh[j * WPITCH + q * 4] = make_uint2(h0, h1);
            *(uint2*)&sWl[j * WPITCH + q * 4] = make_uint2(l0, l1);
        }
        // ---- stage Act tile [32 k][128 s] hi/lo (natural layout, coalesced) ----
        #pragma unroll
        for (int i = 0; i < 4; i++) {
            int idx = i * 256 + tid;
            int kk = idx >> 5;
            int s4 = (idx & 31) * 4;
            float4 v = *(const float4*)&Ap[(long long)(k0 + kk) * HW + s0 + s4];
            uint32_t h0, l0, h1, l1;
            split_pack(v.x, v.y, h0, l0);
            split_pack(v.z, v.w, h1, l1);
            *(uint2*)&sAh[kk * APITCH + s4] = make_uint2(h0, h1);
            *(uint2*)&sAl[kk * APITCH + s4] = make_uint2(l0, l1);
        }
        __syncthreads();

        #pragma unroll
        for (int kh = 0; kh < 2; kh++) {
            // A fragments: 2 m-tiles, hi & lo
            uint32_t ah[2][4], al[2][4];
            #pragma unroll
            for (int mt = 0; mt < 2; mt++) {
                uint32_t off = (uint32_t)((mbase + mt * 16 + lrow) * (WPITCH * 2)
                                          + kh * 32 + lhalf * 16);
                ldsm_x4(ah[mt], uWh + off);
                ldsm_x4(al[mt], uWl + off);
            }
            // B fragments: 4 n-pairs (each covers 2 n8-tiles)
            #pragma unroll
            for (int np = 0; np < 4; np++) {
                uint32_t boff = (uint32_t)((kh * 16 + lrow) * (APITCH * 2)
                                           + (nbase + np * 16 + lhalf * 8) * 2);
                uint32_t bh[4], bl[4];
                ldsm_x4_t(bh, uAh + boff);
                ldsm_x4_t(bl, uAl + boff);
                #pragma unroll
                for (int nt2 = 0; nt2 < 2; nt2++) {
                    const uint32_t bh0 = bh[nt2 * 2], bh1 = bh[nt2 * 2 + 1];
                    const uint32_t bl0 = bl[nt2 * 2], bl1 = bl[nt2 * 2 + 1];
                    const int nt = np * 2 + nt2;
                    #pragma unroll
                    for (int mt = 0; mt < 2; mt++) {
                        float* cp = acc + (mt * 8 + nt) * 4;
                        mma_bf16(cp, ah[mt], bh0, bh1);
                        mma_bf16(cp, ah[mt], bl0, bl1);
                        mma_bf16(cp, al[mt], bh0, bh1);
                    }
                }
            }
        }
        __syncthreads();
    }

    // ---- epilogue ----
    const int crow = lane >> 2;
    const int ccol = (lane & 3) * 2;
    #pragma unroll
    for (int mt = 0; mt < 2; mt++) {
        #pragma unroll
        for (int nt = 0; nt < 8; nt++) {
            const float* cp = acc + (mt * 8 + nt) * 4;
            float* p = Op + (long long)(mbase + mt * 16 + crow) * HW
                          + nbase + nt * 8 + ccol;
            *(float2*)p            = make_float2(cp[0], cp[1]);
            *(float2*)(p + 8 * HW) = make_float2(cp[2], cp[3]);
        }
    }
}

// ---------------------------------------------------------------------------
// QK^T partials + sumsq partials. grid = (NCHUNK_QK, B*HD), 256 threads.
// ---------------------------------------------------------------------------
__global__ __launch_bounds__(256) void qk_partial_kernel(
    const float* __restrict__ qbuf, const float* __restrict__ kvbuf,
    float* __restrict__ Sp, float* __restrict__ ssp)
{
    const int chunk = blockIdx.x;
    const int bh = blockIdx.y;
    const int b  = bh >> 3;
    const int h  = bh & 7;
    const float* q = qbuf  + ((long long)b * C   + h * DC) * HW;
    const float* k = kvbuf + ((long long)b * KVC + h * DC) * HW;
    const int nbase = chunk * (HW / NCHUNK_QK);

    __shared__ float QsT[64][49];
    __shared__ float KsT[64][49];

    const int tid = threadIdx.x;
    const int tm = tid >> 4;
    const int tn = tid & 15;

    float acc[3][3] = {};
    float ssq = 0.f;

    for (int t = 0; t < (HW / NCHUNK_QK); t += 64) {
        const int n0 = nbase + t;
        for (int i = tid; i < DC * 64; i += 256) {
            int c  = i >> 6;
            int nn = i & 63;
            QsT[nn][c] = q[(long long)c * HW + n0 + nn];
            KsT[nn][c] = k[(long long)c * HW + n0 + nn];
        }
        __syncthreads();
        #pragma unroll 8
        for (int kk = 0; kk < 64; kk++) {
            float ra[3], rb[3];
            #pragma unroll
            for (int i = 0; i < 3; i++) ra[i] = QsT[kk][tm * 3 + i];
            #pragma unroll
            for (int j = 0; j < 3; j++) rb[j] = KsT[kk][tn * 3 + j];
            #pragma unroll
            for (int i = 0; i < 3; i++)
                #pragma unroll
                for (int j = 0; j < 3; j++)
                    acc[i][j] = fmaf(ra[i], rb[j], acc[i][j]);
        }
        if (tid < 2 * DC) {
            const int r = (tid < DC) ? tid : tid - DC;
            #pragma unroll 8
            for (int nn = 0; nn < 64; nn++) {
                float v = (tid < DC) ? QsT[nn][r] : KsT[nn][r];
                ssq = fmaf(v, v, ssq);
            }
        }
        __syncthreads();
    }

    float* Sout = Sp + ((long long)chunk * (B * HD) + bh) * (DC * DC);
    #pragma unroll
    for (int i = 0; i < 3; i++)
        #pragma unroll
        for (int j = 0; j < 3; j++)
            Sout[(tm * 3 + i) * DC + tn * 3 + j] = acc[i][j];

    if (tid < 2 * DC)
        ssp[((long long)chunk * (B * HD) + bh) * (2 * DC) + tid] = ssq;
}

// ---------------------------------------------------------------------------
// Reduce partials, apply norms + temperature, softmax. 128 blocks, 256 thr.
// ---------------------------------------------------------------------------
__global__ __launch_bounds__(256) void softmax_kernel(
    const float* __restrict__ Sp, const float* __restrict__ ssp,
    const float* __restrict__ temperature, float* __restrict__ Sout)
{
    const int bh = blockIdx.x;
    const int h  = bh & 7;
    const int tid = threadIdx.x;

    __shared__ float S[DC][DC + 1];
    __shared__ float invq[DC], invk[DC];

    for (int i = tid; i < DC * DC; i += 256) {
        float s = 0.f;
        #pragma unroll
        for (int ch = 0; ch < NCHUNK_QK; ch++)
            s += Sp[((long long)ch * (B * HD) + bh) * (DC * DC) + i];
        S[i / DC][i % DC] = s;
    }
    if (tid < 2 * DC) {
        float s = 0.f;
        #pragma unroll
        for (int ch = 0; ch < NCHUNK_QK; ch++)
            s += ssp[((long long)ch * (B * HD) + bh) * (2 * DC) + tid];
        float inv = 1.0f / fmaxf(sqrtf(s), 1e-12f);
        if (tid < DC) invq[tid] = inv; else invk[tid - DC] = inv;
    }
    __syncthreads();

    if (tid < DC) {
        const float t = temperature[h];
        const float iq = invq[tid] * t;
        float m = -INFINITY;
        float row[DC];
        #pragma unroll 8
        for (int d = 0; d < DC; d++) {
            float v = S[tid][d] * iq * invk[d];
            row[d] = v;
            m = fmaxf(m, v);
        }
        float sum = 0.f;
        #pragma unroll 8
        for (int d = 0; d < DC; d++) {
            float e = expf(row[d] - m);
            row[d] = e;
            sum += e;
        }
        float inv = 1.0f / sum;
        #pragma unroll 8
        for (int d = 0; d < DC; d++)
            Sout[(long long)bh * (DC * DC) + tid * DC + d] = row[d] * inv;
    }
}

// ---------------------------------------------------------------------------
// O = S * V, spatial-split. grid = (NCHUNK_SV, B*HD), 256 threads.
// ---------------------------------------------------------------------------
__global__ __launch_bounds__(256) void sv_kernel(
    const float* __restrict__ Sg, const float* __restrict__ kvbuf,
    float* __restrict__ obuf)
{
    const int chunk = blockIdx.x;
    const int bh = blockIdx.y;
    const int b  = bh >> 3;
    const int h  = bh & 7;
    const float* v = kvbuf + ((long long)b * KVC + C + h * DC) * HW;
    float*       o = obuf  + ((long long)b * C   + h * DC) * HW;
    const int nbase = chunk * (HW / NCHUNK_SV);

    __shared__ float S[DC][DC + 1];
    __shared__ float Vs[DC][68];

    const int tid = threadIdx.x;
    const int tm = tid >> 4;
    const int tn = tid & 15;
    const int tn4 = tn * 4;

    for (int i = tid; i < DC * DC; i += 256)
        S[i / DC][i % DC] = Sg[(long long)bh * (DC * DC) + i];
    __syncthreads();

    for (int t = 0; t < (HW / NCHUNK_SV); t += 64) {
        const int n0 = nbase + t;
        for (int i = tid; i < DC * 64; i += 256) {
            int d  = i >> 6;
            int nn = i & 63;
            Vs[d][nn] = v[(long long)d * HW + n0 + nn];
        }
        __syncthreads();
        float acc2[3][4] = {};
        #pragma unroll 4
        for (int d = 0; d < DC; d++) {
            float rs[3];
            #pragma unroll
            for (int i = 0; i < 3; i++) rs[i] = S[tm * 3 + i][d];
            float4 rv = *(const float4*)&Vs[d][tn4];
            #pragma unroll
            for (int i = 0; i < 3; i++) {
                acc2[i][0] = fmaf(rs[i], rv.x, acc2[i][0]);
                acc2[i][1] = fmaf(rs[i], rv.y, acc2[i][1]);
                acc2[i][2] = fmaf(rs[i], rv.z, acc2[i][2]);
                acc2[i][3] = fmaf(rs[i], rv.w, acc2[i][3]);
            }
        }
        #pragma unroll
        for (int i = 0; i < 3; i++) {
            *(float4*)&o[(long long)(tm * 3 + i) * HW + n0 + tn4] =
                make_float4(acc2[i][0], acc2[i][1], acc2[i][2], acc2[i][3]);
        }
        __syncthreads();
    }
}

// ---------------------------------------------------------------------------
// Launch
// ---------------------------------------------------------------------------
extern "C" void kernel_launch(void* const* d_in, const int* in_sizes, int n_in,
                              void* d_out, int out_size)
{
    const float* x           = (const float*)d_in[0];
    const float* query       = (const float*)d_in[1];
    const float* w_kv        = (const float*)d_in[2];
    const float* w_q         = (const float*)d_in[3];
    const float* w_proj      = (const float*)d_in[4];
    const float* temperature = (const float*)d_in[5];
    float* out = (float*)d_out;

    float *kv, *qb, *ob, *Sp, *ssp, *S;
    cudaGetSymbolAddress((void**)&kv,  g_kv);
    cudaGetSymbolAddress((void**)&qb,  g_q);
    cudaGetSymbolAddress((void**)&ob,  g_o);
    cudaGetSymbolAddress((void**)&Sp,  g_Sp);
    cudaGetSymbolAddress((void**)&ssp, g_ssp);
    cudaGetSymbolAddress((void**)&S,   g_S);

    // 1) kv = w_kv @ x        [768 x 384] x [384 x 4096] per batch
    gemm_bf16s_kernel<C><<<dim3(HW / 128, KVC / 128, B), 256>>>(w_kv, x, kv, KVC);

    // 2) q = w_q @ query      [384 x 192] x [192 x 4096] per batch
    gemm_bf16s_kernel<QC><<<dim3(HW / 128, C / 128, B), 256>>>(w_q, query, qb, C);

    // 3) QK^T partials + sumsq partials
    qk_partial_kernel<<<dim3(NCHUNK_QK, B * HD), 256>>>(qb, kv, Sp, ssp);

    // 4) reduce + norm-scale + softmax
    softmax_kernel<<<B * HD, 256>>>(Sp, ssp, temperature, S);

    // 5) O = S * V
    sv_kernel<<<dim3(NCHUNK_SV, B * HD), 256>>>(S, kv, ob);

    // 6) out = w_proj @ o     [384 x 384] x [384 x 4096] per batch
    gemm_bf16s_kernel<C><<<dim3(HW / 128, C / 128, B), 256>>>(w_proj, ob, out, C);
}